// round 4
// baseline (speedup 1.0000x reference)
#include <cuda_runtime.h>

// Deriv2Matern52: out[i,a,j,b] = c^2 * ( (a==b)*A(i,j)*inv_l2[a] - 5*fr(i,j)*D[i,j,a]*D[i,j,b] )
//
// Fully register-resident version: no smem, no syncthreads.
// Thread t handles pair p = t>>1 (j = j0+p), half = t&1 (b in [4*half, 4*half+4)).
// Each thread recomputes its pair's scalars from global inputs (X1 row is
// block-uniform; X2 row shared by 2 adjacent lanes -> L1 broadcast).
// Warp store pattern: lane t writes 16B at base+16*t -> each STG.128 is a
// fully contiguous 512B warp transaction (full 32B sectors).

#define D_DIM 8
#define JT 256          // j-tile per block
#define NTHREADS 512    // 2 threads per pair
#define SQRT5F 2.2360679774997896f

__global__ __launch_bounds__(NTHREADS) void deriv2_matern52_kernel(
    const float* __restrict__ X1,   // [n, 8]
    const float* __restrict__ X2,   // [m, 8]
    const float* __restrict__ cptr, // [1]
    const float* __restrict__ lptr, // [8]
    float* __restrict__ out,        // [n, 8, m, 8]
    int m)
{
    const int t    = threadIdx.x;
    const int i    = blockIdx.y;
    const int p    = t >> 1;            // pair index within tile
    const int half = t & 1;
    const int hb   = half * 4;
    const int j    = blockIdx.x * JT + p;

    // lengthscales -> inv_l2 (uniform, L1-resident)
    float invl2[D_DIM];
#pragma unroll
    for (int a = 0; a < D_DIM; a++) {
        float lv = __ldg(lptr + a);
        invl2[a] = 1.0f / (lv * lv);
    }
    float cv = __ldg(cptr);
    float c2 = cv * cv;

    const float4* x1p = reinterpret_cast<const float4*>(X1 + (size_t)i * D_DIM);
    const float4* x2p = reinterpret_cast<const float4*>(X2 + (size_t)j * D_DIM);
    float4 x1a = __ldg(x1p);
    float4 x1b = __ldg(x1p + 1);
    float4 x2a = __ldg(x2p);
    float4 x2b = __ldg(x2p + 1);

    float dx[D_DIM];
    dx[0] = x1a.x - x2a.x; dx[1] = x1a.y - x2a.y;
    dx[2] = x1a.z - x2a.z; dx[3] = x1a.w - x2a.w;
    dx[4] = x1b.x - x2b.x; dx[5] = x1b.y - x2b.y;
    dx[6] = x1b.z - x2b.z; dx[7] = x1b.w - x2b.w;

    float s = 0.0f;
    float Dv[D_DIM];
#pragma unroll
    for (int a = 0; a < D_DIM; a++) {
        Dv[a] = dx[a] * invl2[a];
        s = fmaf(dx[a], Dv[a], s);
    }
    float r   = sqrtf(s);
    float fr  = (5.0f / 3.0f) * __expf(-SQRT5F * r);
    float A   = fr * fmaf(SQRT5F, r, 1.0f);
    float Ac2 = A * c2;
    float m5  = -5.0f * fr * c2;

    // diagonal contributions for this thread's b-range
    float Ad[4];
#pragma unroll
    for (int x = 0; x < 4; x++)
        Ad[x] = Ac2 * invl2[hb + x];

    // base element index of (i, a=0, j, b=hb)
    float* dst = out + ((((size_t)i * D_DIM) * (size_t)m + (size_t)j) * D_DIM) + hb;
    const size_t astride = (size_t)m * D_DIM;

#pragma unroll
    for (int a = 0; a < D_DIM; a++) {
        float ta = m5 * Dv[a];
        float o0 = ta * Dv[hb + 0];
        float o1 = ta * Dv[hb + 1];
        float o2 = ta * Dv[hb + 2];
        float o3 = ta * Dv[hb + 3];
        if ((a >> 2) == half) {
            int x = a & 3;
            float add = Ad[x];
            if (x == 0) o0 += add;
            else if (x == 1) o1 += add;
            else if (x == 2) o2 += add;
            else o3 += add;
        }
        __stcs(reinterpret_cast<float4*>(dst + (size_t)a * astride),
               make_float4(o0, o1, o2, o3));
    }
}

extern "C" void kernel_launch(void* const* d_in, const int* in_sizes, int n_in,
                              void* d_out, int out_size)
{
    const float* X1 = (const float*)d_in[0];
    const float* X2 = (const float*)d_in[1];
    const float* c  = (const float*)d_in[2];
    const float* l  = (const float*)d_in[3];
    float* out = (float*)d_out;

    int n = in_sizes[0] / D_DIM;
    int m = in_sizes[1] / D_DIM;

    dim3 grid(m / JT, n);
    deriv2_matern52_kernel<<<grid, NTHREADS>>>(X1, X2, c, l, out, m);
}